// round 8
// baseline (speedup 1.0000x reference)
#include <cuda_runtime.h>
#include <cuda_fp16.h>
#include <mma.h>
#include <cstdint>

using namespace nvcuda;

// ---------------------------------------------------------------------------
// Problem constants
// ---------------------------------------------------------------------------
#define NB      2
#define LQ      19560
#define DMODEL  256
#define NHEADS  8
#define NLEV    4
#define NPTS    4
#define HDIM    32
#define NROWS   (NB * LQ)   // 39120
#define KSTRIDE 256

// FPN level shapes (fixed by the problem definition)
__device__ __constant__ const int LVL_H[4] = {92, 46, 23, 12};
__device__ __constant__ const int LVL_W[4] = {160, 80, 40, 20};
__device__ __constant__ const int LVL_S[4] = {0, 14720, 18400, 19320};

// ---------------------------------------------------------------------------
// Device scratch (static; no cudaMalloc allowed)
// ---------------------------------------------------------------------------
__device__ __align__(256) __half g_value[2 * NROWS * DMODEL];
__device__ __align__(256) float  g_off[2 * NROWS * DMODEL];
__device__ __align__(256) float  g_aw[2 * NROWS * 128];
__device__ __align__(256) float  g_d[2 * NROWS * DMODEL];
__device__ __align__(256) float  g_Wf0[DMODEL * DMODEL];     // W_o @ W_agg_top (f32)
__device__ __align__(256) float  g_Wf1[DMODEL * DMODEL];
__device__ __align__(256) __half g_Whv[DMODEL * DMODEL];     // half, K-major
__device__ __align__(256) __half g_Whso[DMODEL * DMODEL];
__device__ __align__(256) __half g_Whaw[128 * DMODEL];
__device__ __align__(256) __half g_Whf0[DMODEL * DMODEL];
__device__ __align__(256) __half g_Whf1[DMODEL * DMODEL];
__device__ __align__(256) float  g_bf[DMODEL];

// ---------------------------------------------------------------------------
// FFMA SGEMM (tiny weight-prep GEMMs only)
// ---------------------------------------------------------------------------
#define BM 128
#define BN 64
#define BK 16

__global__ __launch_bounds__(256) void sgemm_kernel(
    const float* __restrict__ A, const float* __restrict__ B,
    const float* __restrict__ bias, float* __restrict__ C,
    int M, int K, int N)
{
    __shared__ float As[BK][BM];
    __shared__ float Bs[BK][BN];

    const int tid = threadIdx.x;
    const int tx = tid & 15;
    const int ty = tid >> 4;
    const int block_row = blockIdx.y * BM;
    const int block_col = blockIdx.x * BN;

    float acc[8][4];
#pragma unroll
    for (int i = 0; i < 8; i++)
#pragma unroll
        for (int j = 0; j < 4; j++) acc[i][j] = 0.f;

    for (int k0 = 0; k0 < K; k0 += BK) {
#pragma unroll
        for (int i = 0; i < 2; i++) {
            int idx = tid + i * 256;
            int r = idx >> 2;
            int kv = idx & 3;
            int grow = block_row + r;
            float4 v = make_float4(0.f, 0.f, 0.f, 0.f);
            if (grow < M)
                v = *(const float4*)&A[(size_t)grow * K + k0 + kv * 4];
            As[kv * 4 + 0][r] = v.x;
            As[kv * 4 + 1][r] = v.y;
            As[kv * 4 + 2][r] = v.z;
            As[kv * 4 + 3][r] = v.w;
        }
        {
            int r = tid >> 4;
            int cv = tid & 15;
            float4 v = *(const float4*)&B[(size_t)(k0 + r) * N + block_col + cv * 4];
            *(float4*)&Bs[r][cv * 4] = v;
        }
        __syncthreads();

#pragma unroll
        for (int kk = 0; kk < BK; kk++) {
            float4 a0 = *(const float4*)&As[kk][ty * 8];
            float4 a1 = *(const float4*)&As[kk][ty * 8 + 4];
            float4 b0 = *(const float4*)&Bs[kk][tx * 4];
            float ar[8] = {a0.x, a0.y, a0.z, a0.w, a1.x, a1.y, a1.z, a1.w};
            float br[4] = {b0.x, b0.y, b0.z, b0.w};
#pragma unroll
            for (int i = 0; i < 8; i++)
#pragma unroll
                for (int j = 0; j < 4; j++)
                    acc[i][j] = fmaf(ar[i], br[j], acc[i][j]);
        }
        __syncthreads();
    }

#pragma unroll
    for (int i = 0; i < 8; i++) {
        int grow = block_row + ty * 8 + i;
        if (grow < M) {
#pragma unroll
            for (int j = 0; j < 4; j++) {
                int gcol = block_col + tx * 4 + j;
                float v = acc[i][j];
                if (bias) v += bias[gcol];
                C[(size_t)grow * N + gcol] = v;
            }
        }
    }
}

// ---------------------------------------------------------------------------
// fp16 wmma GEMM (m16n16k16, fp32 accum).
//   C[M,NT] = A_cat @ B_cat + bias.
//   K-concat: chunks >= chunksA switch to (A1, B1) column sources.
//   Row-concat: rows >= rowSplit read from A2 (row - rowSplit).
//   A fp32 row-major [*,256] (converted to half on SMEM load);
//   B half K-major [NT,256].  EPI: 0 = f32 out, 1 = f16 out.
// ---------------------------------------------------------------------------
template <int NT, int EPI>
__global__ __launch_bounds__(256) void gemm_hmma(
    const float* __restrict__ A0, const float* __restrict__ A1,
    const float* __restrict__ A2, int rowSplit, int chunksA,
    const __half* __restrict__ B0, const __half* __restrict__ B1, int chunksTot,
    const float* __restrict__ bias, void* __restrict__ Cout, int M)
{
    __shared__ __align__(128) union {
        struct { __half A[128][72]; __half B[64][72]; } ld;  // 27648 B
        float C[128][72];                                    // 36864 B
    } sm;

    const int tid = threadIdx.x;
    const int wid = tid >> 5;
    const int wm = (wid & 3) * 32;       // 4 m-warps
    const int wn = (wid >> 2) * 32;      // 2 n-warps
    const int mbase = blockIdx.y * 128;
    const int ncol0 = blockIdx.x * 64;

    wmma::fragment<wmma::accumulator, 16, 16, 16, float> acc[2][2];
#pragma unroll
    for (int i = 0; i < 2; i++)
#pragma unroll
        for (int j = 0; j < 2; j++) wmma::fill_fragment(acc[i][j], 0.f);

    for (int c = 0; c < chunksTot; ++c) {
        const float* Ac; const __half* Bp; int kloc;
        if (c < chunksA) { Ac = A0; Bp = B0; kloc = c * 64; }
        else             { Ac = A1; Bp = B1; kloc = (c - chunksA) * 64; }

        // A tile: 128 rows x 64 f32 -> half
#pragma unroll
        for (int i = tid; i < 2048; i += 256) {
            const int row = i >> 4, j = i & 15;
            const int grow = mbase + row;
            float4 v = make_float4(0.f, 0.f, 0.f, 0.f);
            if (grow < M) {
                const float* src; int rr;
                if (grow < rowSplit) { src = Ac; rr = grow; }
                else                 { src = A2; rr = grow - rowSplit; }
                v = *(const float4*)&src[(size_t)rr * KSTRIDE + kloc + j * 4];
            }
            *(__half2*)&sm.ld.A[row][j * 4]     = __floats2half2_rn(v.x, v.y);
            *(__half2*)&sm.ld.A[row][j * 4 + 2] = __floats2half2_rn(v.z, v.w);
        }
        // B tile: 64 K-major rows x 64 halves
#pragma unroll
        for (int i = tid; i < 512; i += 256) {
            const int row = i >> 3, j = i & 7;
            int4 v = *(const int4*)&Bp[(size_t)(ncol0 + row) * KSTRIDE + kloc + j * 8];
            *(int4*)&sm.ld.B[row][j * 8] = v;
        }
        __syncthreads();

#pragma unroll
        for (int kk = 0; kk < 64; kk += 16) {
            wmma::fragment<wmma::matrix_a, 16, 16, 16, __half, wmma::row_major> a0, a1;
            wmma::fragment<wmma::matrix_b, 16, 16, 16, __half, wmma::col_major> b0, b1;
            wmma::load_matrix_sync(a0, &sm.ld.A[wm][kk], 72);
            wmma::load_matrix_sync(a1, &sm.ld.A[wm + 16][kk], 72);
            wmma::load_matrix_sync(b0, &sm.ld.B[wn][kk], 72);
            wmma::load_matrix_sync(b1, &sm.ld.B[wn + 16][kk], 72);
            wmma::mma_sync(acc[0][0], a0, b0, acc[0][0]);
            wmma::mma_sync(acc[0][1], a0, b1, acc[0][1]);
            wmma::mma_sync(acc[1][0], a1, b0, acc[1][0]);
            wmma::mma_sync(acc[1][1], a1, b1, acc[1][1]);
        }
        __syncthreads();
    }

    // epilogue via SMEM
    wmma::store_matrix_sync(&sm.C[wm][wn],           acc[0][0], 72, wmma::mem_row_major);
    wmma::store_matrix_sync(&sm.C[wm][wn + 16],      acc[0][1], 72, wmma::mem_row_major);
    wmma::store_matrix_sync(&sm.C[wm + 16][wn],      acc[1][0], 72, wmma::mem_row_major);
    wmma::store_matrix_sync(&sm.C[wm + 16][wn + 16], acc[1][1], 72, wmma::mem_row_major);
    __syncthreads();

#pragma unroll
    for (int i = tid; i < 128 * 16; i += 256) {
        const int row = i >> 4, j = i & 15;
        const int grow = mbase + row;
        if (grow < M) {
            const int col = ncol0 + j * 4;
            float4 v = *(const float4*)&sm.C[row][j * 4];
            if (bias) {
                v.x += bias[col + 0]; v.y += bias[col + 1];
                v.z += bias[col + 2]; v.w += bias[col + 3];
            }
            if (EPI == 0) {
                *(float4*)((float*)Cout + (size_t)grow * NT + col) = v;
            } else {
                __half* Cp = (__half*)Cout + (size_t)grow * NT + col;
                *(__half2*)(Cp)     = __floats2half2_rn(v.x, v.y);
                *(__half2*)(Cp + 2) = __floats2half2_rn(v.z, v.w);
            }
        }
    }
}

// ---------------------------------------------------------------------------
// Transpose fp32 -> half, K-major:  out[C][R] = half(in[R][C])
// ---------------------------------------------------------------------------
__global__ void transpose_h_kernel(const float* __restrict__ in, __half* __restrict__ out,
                                   int R, int C)
{
    __shared__ float t[32][33];
    int bx = blockIdx.x * 32, by = blockIdx.y * 32;
    int x = bx + threadIdx.x;
#pragma unroll
    for (int i = 0; i < 32; i += 8) {
        int y = by + threadIdx.y + i;
        if (x < C && y < R) t[threadIdx.y + i][threadIdx.x] = in[(size_t)y * C + x];
    }
    __syncthreads();
    int x2 = by + threadIdx.x;
#pragma unroll
    for (int i = 0; i < 32; i += 8) {
        int y2 = bx + threadIdx.y + i;
        if (x2 < R && y2 < C) out[(size_t)y2 * R + x2] = __float2half(t[threadIdx.x][threadIdx.y + i]);
    }
}

// ---------------------------------------------------------------------------
// bf[j] = b_agg[j] + sum_m b_o[m] * (W_agg[m][j] + W_agg[m+256][j])
// ---------------------------------------------------------------------------
__global__ void fuse_bias_kernel(const float* __restrict__ b_o,
                                 const float* __restrict__ b_agg,
                                 const float* __restrict__ W_agg,
                                 float* __restrict__ bf)
{
    int j = threadIdx.x;
    float s = b_agg[j];
    for (int m = 0; m < DMODEL; m++)
        s += b_o[m] * (W_agg[(size_t)m * DMODEL + j] +
                       W_agg[(size_t)(m + DMODEL) * DMODEL + j]);
    bf[j] = s;
}

// ---------------------------------------------------------------------------
// Joint softmax over 32 = concat(aw0[16], aw1[16]) per (n,q,h); in-place.
// ---------------------------------------------------------------------------
__global__ void softmax_kernel(float* __restrict__ aw0, float* __restrict__ aw1,
                               int total)
{
    int t = blockIdx.x * blockDim.x + threadIdx.x;
    if (t >= total) return;
    float4* p0 = (float4*)(aw0 + (size_t)t * 16);
    float4* p1 = (float4*)(aw1 + (size_t)t * 16);
    float v[32];
    float4 r;
#pragma unroll
    for (int i = 0; i < 4; i++) {
        r = p0[i]; v[i*4+0]=r.x; v[i*4+1]=r.y; v[i*4+2]=r.z; v[i*4+3]=r.w;
    }
#pragma unroll
    for (int i = 0; i < 4; i++) {
        r = p1[i]; v[16+i*4+0]=r.x; v[16+i*4+1]=r.y; v[16+i*4+2]=r.z; v[16+i*4+3]=r.w;
    }
    float mx = v[0];
#pragma unroll
    for (int i = 1; i < 32; i++) mx = fmaxf(mx, v[i]);
    float sum = 0.f;
#pragma unroll
    for (int i = 0; i < 32; i++) { v[i] = expf(v[i] - mx); sum += v[i]; }
    float inv = 1.f / sum;
#pragma unroll
    for (int i = 0; i < 32; i++) v[i] *= inv;
#pragma unroll
    for (int i = 0; i < 4; i++)
        p0[i] = make_float4(v[i*4+0], v[i*4+1], v[i*4+2], v[i*4+3]);
#pragma unroll
    for (int i = 0; i < 4; i++)
        p1[i] = make_float4(v[16+i*4+0], v[16+i*4+1], v[16+i*4+2], v[16+i*4+3]);
}

// ---------------------------------------------------------------------------
// Deformable sampling, head-pair version.
//   One warp = (n,q, head-pair); each half-warp = one head, 16 lanes x half2
//   (2 channels/lane).  blockIdx.y = iter.  Width-16 shuffles keep half-warps
//   independent; x/y/bounds are uniform per half-warp.
// ---------------------------------------------------------------------------
__global__ __launch_bounds__(256) void sample2_kernel(
    const __half* __restrict__ value,  // [2][N,Len,8,32]
    const float* __restrict__ ref,     // (N,Lq,4,2)
    const float* __restrict__ off,     // [2][N,Lq,8,32]
    const float* __restrict__ attn,    // [2][N,Lq,8,16]
    float* __restrict__ out)           // [2][N,Lq,256]
{
    const int iter = blockIdx.y;
    const int gwarp = blockIdx.x * 8 + (threadIdx.x >> 5);
    const int lane = threadIdx.x & 31;
    if (gwarp >= NROWS * 4) return;

    const int hp = gwarp & 3;
    const int nq = gwarp >> 2;
    const int n = nq / LQ;
    const int h = hp * 2 + (lane >> 4);
    const int s = lane & 15;

    const __half* val_it = value + (size_t)iter * NROWS * DMODEL;
    const float* off_it  = off   + (size_t)iter * NROWS * DMODEL;
    const float* attn_it = attn  + (size_t)iter * NROWS * 128;
    float* out_it        = out   + (size_t)iter * NROWS * DMODEL;

    // per-head metadata in lanes of this half-warp
    const float offA = off_it[((size_t)nq * NHEADS + h) * 32 + s];        // vals 0..15
    const float offB = off_it[((size_t)nq * NHEADS + h) * 32 + 16 + s];   // vals 16..31
    const float attv = attn_it[((size_t)nq * NHEADS + h) * 16 + s];
    const float refv = (s < 8) ? ref[(size_t)nq * 8 + s] : 0.f;

    float accx = 0.f, accy = 0.f;

#pragma unroll
    for (int l = 0; l < NLEV; l++) {
        const int H = LVL_H[l], W = LVL_W[l], st = LVL_S[l];
        const float fW = (float)W, fH = (float)H;
        const float rx = __shfl_sync(0xFFFFFFFFu, refv, l * 2 + 0, 16);
        const float ry = __shfl_sync(0xFFFFFFFFu, refv, l * 2 + 1, 16);
        const __half* vbase =
            val_it + (((size_t)n * LQ + st) * NHEADS + h) * HDIM + 2 * s;

#pragma unroll
        for (int p = 0; p < NPTS; p++) {
            const int sp = l * 4 + p;
            float ox, oy;
            if (sp < 8) {
                ox = __shfl_sync(0xFFFFFFFFu, offA, sp * 2 + 0, 16);
                oy = __shfl_sync(0xFFFFFFFFu, offA, sp * 2 + 1, 16);
            } else {
                ox = __shfl_sync(0xFFFFFFFFu, offB, sp * 2 - 16, 16);
                oy = __shfl_sync(0xFFFFFFFFu, offB, sp * 2 - 15, 16);
            }
            const float a = __shfl_sync(0xFFFFFFFFu, attv, sp, 16);

            // match reference arithmetic order exactly
            float x = (rx + ox / fW) * fW - 0.5f;
            float y = (ry + oy / fH) * fH - 0.5f;
            float x0f = floorf(x), y0f = floorf(y);
            int x0 = (int)x0f, y0 = (int)y0f;
            float lx = x - x0f, ly = y - y0f;
            float hx = 1.f - lx, hy = 1.f - ly;

            float smpx = 0.f, smpy = 0.f;
            const bool xin0 = (x0 >= 0) & (x0 < W);
            const bool xin1 = (x0 + 1 >= 0) & (x0 + 1 < W);
            const bool yin0 = (y0 >= 0) & (y0 < H);
            const bool yin1 = (y0 + 1 >= 0) & (y0 + 1 < H);
            if (xin0 & yin0) {
                float2 v = __half22float2(*(const __half2*)(vbase + (size_t)(y0 * W + x0) * DMODEL));
                float w = hy * hx; smpx = fmaf(w, v.x, smpx); smpy = fmaf(w, v.y, smpy);
            }
            if (xin1 & yin0) {
                float2 v = __half22float2(*(const __half2*)(vbase + (size_t)(y0 * W + x0 + 1) * DMODEL));
                float w = hy * lx; smpx = fmaf(w, v.x, smpx); smpy = fmaf(w, v.y, smpy);
            }
            if (xin0 & yin1) {
                float2 v = __half22float2(*(const __half2*)(vbase + (size_t)((y0 + 1) * W + x0) * DMODEL));
                float w = ly * hx; smpx = fmaf(w, v.x, smpx); smpy = fmaf(w, v.y, smpy);
            }
            if (xin1 & yin1) {
                float2 v = __half22float2(*(const __half2*)(vbase + (size_t)((y0 + 1) * W + x0 + 1) * DMODEL));
                float w = ly * lx; smpx = fmaf(w, v.x, smpx); smpy = fmaf(w, v.y, smpy);
            }
            accx = fmaf(a, smpx, accx);
            accy = fmaf(a, smpy, accy);
        }
    }

    *(float2*)&out_it[(size_t)nq * DMODEL + h * HDIM + 2 * s] = make_float2(accx, accy);
}

// ---------------------------------------------------------------------------
// Launcher
// ---------------------------------------------------------------------------
extern "C" void kernel_launch(void* const* d_in, const int* in_sizes, int n_in,
                              void* d_out, int out_size)
{
    const float* q0     = (const float*)d_in[0];
    const float* q1     = (const float*)d_in[1];
    const float* ref    = (const float*)d_in[2];
    const float* flat0  = (const float*)d_in[3];
    const float* flat1  = (const float*)d_in[4];
    const float* W_so   = (const float*)d_in[7];
    const float* b_so   = (const float*)d_in[8];
    const float* W_aw   = (const float*)d_in[9];
    const float* b_aw   = (const float*)d_in[10];
    const float* W_v    = (const float*)d_in[11];
    const float* b_v    = (const float*)d_in[12];
    const float* W_o    = (const float*)d_in[13];
    const float* b_o    = (const float*)d_in[14];
    const float* W_agg  = (const float*)d_in[15];
    const float* b_agg  = (const float*)d_in[16];
    float* out = (float*)d_out;

    __half *value, *Whv, *Whso, *Whaw, *Whf0, *Whf1;
    float *off, *aw, *dd, *Wf0, *Wf1, *bf;
    cudaGetSymbolAddress((void**)&value, g_value);
    cudaGetSymbolAddress((void**)&off, g_off);
    cudaGetSymbolAddress((void**)&aw, g_aw);
    cudaGetSymbolAddress((void**)&dd, g_d);
    cudaGetSymbolAddress((void**)&Wf0, g_Wf0);
    cudaGetSymbolAddress((void**)&Wf1, g_Wf1);
    cudaGetSymbolAddress((void**)&Whv, g_Whv);
    cudaGetSymbolAddress((void**)&Whso, g_Whso);
    cudaGetSymbolAddress((void**)&Whaw, g_Whaw);
    cudaGetSymbolAddress((void**)&Whf0, g_Whf0);
    cudaGetSymbolAddress((void**)&Whf1, g_Whf1);
    cudaGetSymbolAddress((void**)&bf, g_bf);

    dim3 blk(256);
    dim3 tblk(32, 8);
    const int M2 = 2 * NROWS;                 // 78240
    const int MT1 = (NROWS + 127) / 128;      // 306
    const int MT2 = (M2 + 127) / 128;         // 612

    // --- weight prep ---
    transpose_h_kernel<<<dim3(8, 8), tblk>>>(W_v,  Whv,  256, 256);
    transpose_h_kernel<<<dim3(8, 8), tblk>>>(W_so, Whso, 256, 256);
    transpose_h_kernel<<<dim3(4, 8), tblk>>>(W_aw, Whaw, 256, 128);
    sgemm_kernel<<<dim3(4, 2), blk>>>(W_o, W_agg,             nullptr, Wf0, 256, 256, 256);
    sgemm_kernel<<<dim3(4, 2), blk>>>(W_o, W_agg + 256 * 256, nullptr, Wf1, 256, 256, 256);
    fuse_bias_kernel<<<1, DMODEL>>>(b_o, b_agg, W_agg, bf);
    transpose_h_kernel<<<dim3(8, 8), tblk>>>(Wf0, Whf0, 256, 256);
    transpose_h_kernel<<<dim3(8, 8), tblk>>>(Wf1, Whf1, 256, 256);

    // --- row-merged projections (both iters in one launch each) ---
    gemm_hmma<256, 1><<<dim3(4, MT2), blk>>>(flat0, flat0, flat1, NROWS, 4,
                                             Whv, Whv, 4, b_v, value, M2);
    gemm_hmma<256, 0><<<dim3(4, MT2), blk>>>(q0, q0, q1, NROWS, 4,
                                             Whso, Whso, 4, b_so, off, M2);
    gemm_hmma<128, 0><<<dim3(2, MT2), blk>>>(q0, q0, q1, NROWS, 4,
                                             Whaw, Whaw, 4, b_aw, aw, M2);

    // --- joint softmax over 32 ---
    {
        int total = NROWS * NHEADS;
        softmax_kernel<<<(total + 255) / 256, 256>>>(aw, aw + (size_t)NROWS * 128, total);
    }

    // --- deformable sampling: head-pair warps, both iters in one launch ---
    sample2_kernel<<<dim3((NROWS * 4 + 7) / 8, 2), blk>>>(value, ref, off, aw, dd);

    // --- fused output projection: out = d0@Wf0^T + d1@Wf1^T + bf (K=512) ---
    gemm_hmma<256, 0><<<dim3(4, MT1), blk>>>(dd, dd + (size_t)NROWS * DMODEL,
                                             dd, NROWS + NROWS, 4,
                                             Whf0, Whf1, 8, bf, out, NROWS);

    (void)in_sizes; (void)n_in; (void)out_size;
}

// round 10
// speedup vs baseline: 1.1295x; 1.1295x over previous
#include <cuda_runtime.h>
#include <cuda_fp16.h>
#include <mma.h>
#include <cstdint>

using namespace nvcuda;

// ---------------------------------------------------------------------------
// Problem constants
// ---------------------------------------------------------------------------
#define NB      2
#define LQ      19560
#define DMODEL  256
#define NHEADS  8
#define NLEV    4
#define NPTS    4
#define HDIM    32
#define NROWS   (NB * LQ)   // 39120
#define KSTRIDE 256

// ---------------------------------------------------------------------------
// Device scratch (static; no cudaMalloc allowed)
// ---------------------------------------------------------------------------
__device__ __align__(256) __half g_value0[NROWS * DMODEL];
__device__ __align__(256) __half g_value1[NROWS * DMODEL];
__device__ __align__(256) float  g_off0[NROWS * DMODEL];
__device__ __align__(256) float  g_off1[NROWS * DMODEL];
__device__ __align__(256) float  g_aw0[NROWS * 128];
__device__ __align__(256) float  g_aw1[NROWS * 128];
__device__ __align__(256) float  g_d0[NROWS * DMODEL];
__device__ __align__(256) float  g_d1[NROWS * DMODEL];
__device__ __align__(256) __half g_Whv[DMODEL * DMODEL];     // half, K-major
__device__ __align__(256) __half g_Whso[DMODEL * DMODEL];
__device__ __align__(256) __half g_Whaw[128 * DMODEL];
__device__ __align__(256) __half g_Whf0[DMODEL * DMODEL];    // (W_o@W_aggT)^T half
__device__ __align__(256) __half g_Whf1[DMODEL * DMODEL];
__device__ __align__(256) float  g_bf[DMODEL];

// ---------------------------------------------------------------------------
// Batched transpose fp32 -> half, K-major. blockIdx.z selects matrix.
// No pre-barrier returns: out-of-range tiles simply do no loads/stores.
// ---------------------------------------------------------------------------
__global__ void transpose_batch_kernel(
    const float* __restrict__ W_v, const float* __restrict__ W_so,
    const float* __restrict__ W_aw,
    __half* __restrict__ Whv, __half* __restrict__ Whso, __half* __restrict__ Whaw)
{
    const float* in; __half* out; int C;
    if (blockIdx.z == 0)      { in = W_v;  out = Whv;  C = 256; }
    else if (blockIdx.z == 1) { in = W_so; out = Whso; C = 256; }
    else                      { in = W_aw; out = Whaw; C = 128; }
    const int R = 256;

    __shared__ float t[32][33];
    int bx = blockIdx.x * 32, by = blockIdx.y * 32;
    int x = bx + threadIdx.x;
#pragma unroll
    for (int i = 0; i < 32; i += 8) {
        int y = by + threadIdx.y + i;
        if (x < C && y < R) t[threadIdx.y + i][threadIdx.x] = in[(size_t)y * C + x];
    }
    __syncthreads();
    int x2 = by + threadIdx.x;
#pragma unroll
    for (int i = 0; i < 32; i += 8) {
        int y2 = bx + threadIdx.y + i;
        if (x2 < R && y2 < C) out[(size_t)y2 * R + x2] = __float2half(t[threadIdx.x][threadIdx.y + i]);
    }
}

// ---------------------------------------------------------------------------
// wfprep: Whf_i[j][m] = half( sum_k W_o[m][k] * W_agg_i[k][j] )
//   grid (16, 2): blockIdx.y = half-index i; block covers rows m0..m0+15, all j.
// ---------------------------------------------------------------------------
__global__ __launch_bounds__(256) void wfprep_kernel(
    const float* __restrict__ W_o, const float* __restrict__ W_agg,
    __half* __restrict__ Whf0, __half* __restrict__ Whf1)
{
    __shared__ float sA[16][256];
    const float* Wagg = W_agg + (size_t)blockIdx.y * 256 * 256;
    __half* Whf = blockIdx.y ? Whf1 : Whf0;
    const int m0 = blockIdx.x * 16;
    const int tid = threadIdx.x;

    for (int i = tid; i < 16 * 256; i += 256)
        sA[i >> 8][i & 255] = W_o[(size_t)(m0 + (i >> 8)) * 256 + (i & 255)];
    __syncthreads();

    const int j = tid;
    float acc[16];
#pragma unroll
    for (int m = 0; m < 16; m++) acc[m] = 0.f;
    for (int k = 0; k < 256; k++) {
        float b = Wagg[(size_t)k * 256 + j];     // coalesced across threads
#pragma unroll
        for (int m = 0; m < 16; m++) acc[m] = fmaf(sA[m][k], b, acc[m]);
    }
#pragma unroll
    for (int m = 0; m < 16; m++)
        Whf[(size_t)j * 256 + m0 + m] = __float2half(acc[m]);
}

// ---------------------------------------------------------------------------
// bf[j] = b_agg[j] + sum_m b_o[m] * (W_agg[m][j] + W_agg[m+256][j])
// ---------------------------------------------------------------------------
__global__ void fuse_bias_kernel(const float* __restrict__ b_o,
                                 const float* __restrict__ b_agg,
                                 const float* __restrict__ W_agg,
                                 float* __restrict__ bf)
{
    int j = threadIdx.x;
    float s = b_agg[j];
    for (int m = 0; m < DMODEL; m++)
        s += b_o[m] * (W_agg[(size_t)m * DMODEL + j] +
                       W_agg[(size_t)(m + DMODEL) * DMODEL + j]);
    bf[j] = s;
}

// ---------------------------------------------------------------------------
// fp16 wmma GEMM (m16n16k16, fp32 accum).
//   C[M,NT] = concat_K(A0,A1) @ concat_K(B0h,B1h) + bias
//   A fp32 row-major [M,256] per source (converted to half on SMEM load);
//   Bh half K-major [NT,256] per source.
//   CTA tile 128x64, 8 warps of 32x32, K chunked by 64.  EPI: 0=f32, 1=f16.
// ---------------------------------------------------------------------------
template <int NT, int EPI>
__global__ __launch_bounds__(256) void gemm_hmma(
    const float* __restrict__ A0, const float* __restrict__ A1, int chunksA,
    const __half* __restrict__ B0, const __half* __restrict__ B1, int chunksTot,
    const float* __restrict__ bias, void* __restrict__ Cout, int M)
{
    __shared__ __align__(128) union {
        struct { __half A[128][72]; __half B[64][72]; } ld;  // 27648 B
        float C[128][72];                                    // 36864 B
    } sm;

    const int tid = threadIdx.x;
    const int wid = tid >> 5;
    const int wm = (wid & 3) * 32;       // 4 m-warps
    const int wn = (wid >> 2) * 32;      // 2 n-warps
    const int mbase = blockIdx.y * 128;
    const int ncol0 = blockIdx.x * 64;

    wmma::fragment<wmma::accumulator, 16, 16, 16, float> acc[2][2];
#pragma unroll
    for (int i = 0; i < 2; i++)
#pragma unroll
        for (int j = 0; j < 2; j++) wmma::fill_fragment(acc[i][j], 0.f);

    for (int c = 0; c < chunksTot; ++c) {
        const float* Ap; const __half* Bp; int kloc;
        if (c < chunksA) { Ap = A0; Bp = B0; kloc = c * 64; }
        else             { Ap = A1; Bp = B1; kloc = (c - chunksA) * 64; }

        // A tile: 128 rows x 64 f32, convert to half
#pragma unroll
        for (int i = tid; i < 2048; i += 256) {
            const int row = i >> 4, j = i & 15;
            const int grow = mbase + row;
            float4 v = make_float4(0.f, 0.f, 0.f, 0.f);
            if (grow < M) v = *(const float4*)&Ap[(size_t)grow * KSTRIDE + kloc + j * 4];
            *(__half2*)&sm.ld.A[row][j * 4]     = __floats2half2_rn(v.x, v.y);
            *(__half2*)&sm.ld.A[row][j * 4 + 2] = __floats2half2_rn(v.z, v.w);
        }
        // B tile: 64 K-major rows x 64 halves
#pragma unroll
        for (int i = tid; i < 512; i += 256) {
            const int row = i >> 3, j = i & 7;
            int4 v = *(const int4*)&Bp[(size_t)(ncol0 + row) * KSTRIDE + kloc + j * 8];
            *(int4*)&sm.ld.B[row][j * 8] = v;
        }
        __syncthreads();

#pragma unroll
        for (int kk = 0; kk < 64; kk += 16) {
            wmma::fragment<wmma::matrix_a, 16, 16, 16, __half, wmma::row_major> a0, a1;
            wmma::fragment<wmma::matrix_b, 16, 16, 16, __half, wmma::col_major> b0, b1;
            wmma::load_matrix_sync(a0, &sm.ld.A[wm][kk], 72);
            wmma::load_matrix_sync(a1, &sm.ld.A[wm + 16][kk], 72);
            wmma::load_matrix_sync(b0, &sm.ld.B[wn][kk], 72);
            wmma::load_matrix_sync(b1, &sm.ld.B[wn + 16][kk], 72);
            wmma::mma_sync(acc[0][0], a0, b0, acc[0][0]);
            wmma::mma_sync(acc[0][1], a0, b1, acc[0][1]);
            wmma::mma_sync(acc[1][0], a1, b0, acc[1][0]);
            wmma::mma_sync(acc[1][1], a1, b1, acc[1][1]);
        }
        __syncthreads();
    }

    // epilogue via SMEM
    wmma::store_matrix_sync(&sm.C[wm][wn],           acc[0][0], 72, wmma::mem_row_major);
    wmma::store_matrix_sync(&sm.C[wm][wn + 16],      acc[0][1], 72, wmma::mem_row_major);
    wmma::store_matrix_sync(&sm.C[wm + 16][wn],      acc[1][0], 72, wmma::mem_row_major);
    wmma::store_matrix_sync(&sm.C[wm + 16][wn + 16], acc[1][1], 72, wmma::mem_row_major);
    __syncthreads();

#pragma unroll
    for (int i = tid; i < 128 * 16; i += 256) {
        const int row = i >> 4, j = i & 15;
        const int grow = mbase + row;
        if (grow < M) {
            const int col = ncol0 + j * 4;
            float4 v = *(const float4*)&sm.C[row][j * 4];
            if (bias) {
                v.x += bias[col + 0]; v.y += bias[col + 1];
                v.z += bias[col + 2]; v.w += bias[col + 3];
            }
            if (EPI == 0) {
                *(float4*)((float*)Cout + (size_t)grow * NT + col) = v;
            } else {
                __half* Cp = (__half*)Cout + (size_t)grow * NT + col;
                *(__half2*)(Cp)     = __floats2half2_rn(v.x, v.y);
                *(__half2*)(Cp + 2) = __floats2half2_rn(v.z, v.w);
            }
        }
    }
}

// ---------------------------------------------------------------------------
// Joint softmax over 32 = concat(aw0[16], aw1[16]) per (n,q,h); in-place.
// ---------------------------------------------------------------------------
__global__ void softmax_kernel(float* __restrict__ aw0, float* __restrict__ aw1,
                               int total)
{
    int t = blockIdx.x * blockDim.x + threadIdx.x;
    if (t >= total) return;
    float4* p0 = (float4*)(aw0 + (size_t)t * 16);
    float4* p1 = (float4*)(aw1 + (size_t)t * 16);
    float v[32];
    float4 r;
#pragma unroll
    for (int i = 0; i < 4; i++) {
        r = p0[i]; v[i*4+0]=r.x; v[i*4+1]=r.y; v[i*4+2]=r.z; v[i*4+3]=r.w;
    }
#pragma unroll
    for (int i = 0; i < 4; i++) {
        r = p1[i]; v[16+i*4+0]=r.x; v[16+i*4+1]=r.y; v[16+i*4+2]=r.z; v[16+i*4+3]=r.w;
    }
    float mx = v[0];
#pragma unroll
    for (int i = 1; i < 32; i++) mx = fmaxf(mx, v[i]);
    float sum = 0.f;
#pragma unroll
    for (int i = 0; i < 32; i++) { v[i] = expf(v[i] - mx); sum += v[i]; }
    float inv = 1.f / sum;
#pragma unroll
    for (int i = 0; i < 32; i++) v[i] *= inv;
#pragma unroll
    for (int i = 0; i < 4; i++)
        p0[i] = make_float4(v[i*4+0], v[i*4+1], v[i*4+2], v[i*4+3]);
#pragma unroll
    for (int i = 0; i < 4; i++)
        p1[i] = make_float4(v[16+i*4+0], v[16+i*4+1], v[16+i*4+2], v[16+i*4+3]);
}

// ---------------------------------------------------------------------------
// Deformable sampling: one warp per (n,q,h); lane = channel; value in fp16.
// (R7-proven version)
// ---------------------------------------------------------------------------
__global__ __launch_bounds__(256) void sample_kernel(
    const __half* __restrict__ value, const float* __restrict__ ref,
    const float* __restrict__ off, const float* __restrict__ attn,
    const int* __restrict__ shapes, const int* __restrict__ starts,
    float* __restrict__ out)
{
    int gwarp = (blockIdx.x * blockDim.x + threadIdx.x) >> 5;
    int lane = threadIdx.x & 31;
    if (gwarp >= NROWS * NHEADS) return;

    int h = gwarp & 7;
    int nq = gwarp >> 3;
    int n = nq / LQ;

    float my_off  = off[((size_t)nq * NHEADS + h) * 32 + lane];
    float my_attn = (lane < 16) ? attn[((size_t)nq * NHEADS + h) * 16 + lane] : 0.f;
    float my_ref  = (lane < 8)  ? ref[(size_t)nq * 8 + lane] : 0.f;

    float acc = 0.f;

#pragma unroll
    for (int l = 0; l < NLEV; l++) {
        int H = shapes[l * 2 + 0];
        int W = shapes[l * 2 + 1];
        int s = starts[l];
        float fW = (float)W, fH = (float)H;
        float rx = __shfl_sync(0xFFFFFFFFu, my_ref, l * 2 + 0);
        float ry = __shfl_sync(0xFFFFFFFFu, my_ref, l * 2 + 1);
        const __half* vbase =
            value + (((size_t)n * LQ + s) * NHEADS + h) * HDIM + lane;

#pragma unroll
        for (int p = 0; p < NPTS; p++) {
            int sp = l * 4 + p;
            float ox = __shfl_sync(0xFFFFFFFFu, my_off, sp * 2 + 0);
            float oy = __shfl_sync(0xFFFFFFFFu, my_off, sp * 2 + 1);
            float a  = __shfl_sync(0xFFFFFFFFu, my_attn, sp);

            // match reference arithmetic order exactly
            float x = (rx + ox / fW) * fW - 0.5f;
            float y = (ry + oy / fH) * fH - 0.5f;
            float x0f = floorf(x), y0f = floorf(y);
            int x0 = (int)x0f, y0 = (int)y0f;
            float lx = x - x0f, ly = y - y0f;
            float hx = 1.f - lx, hy = 1.f - ly;

            float smp = 0.f;
            bool xin0 = (x0 >= 0) & (x0 < W);
            bool xin1 = (x0 + 1 >= 0) & (x0 + 1 < W);
            bool yin0 = (y0 >= 0) & (y0 < H);
            bool yin1 = (y0 + 1 >= 0) & (y0 + 1 < H);
            if (xin0 & yin0) smp = fmaf(hy * hx, __half2float(__ldg(&vbase[(size_t)(y0 * W + x0) * DMODEL])), smp);
            if (xin1 & yin0) smp = fmaf(hy * lx, __half2float(__ldg(&vbase[(size_t)(y0 * W + x0 + 1) * DMODEL])), smp);
            if (xin0 & yin1) smp = fmaf(ly * hx, __half2float(__ldg(&vbase[(size_t)((y0 + 1) * W + x0) * DMODEL])), smp);
            if (xin1 & yin1) smp = fmaf(ly * lx, __half2float(__ldg(&vbase[(size_t)((y0 + 1) * W + x0 + 1) * DMODEL])), smp);
            acc = fmaf(a, smp, acc);
        }
    }

    out[(size_t)nq * DMODEL + h * HDIM + lane] = acc;
}

// ---------------------------------------------------------------------------
// Launcher
// ---------------------------------------------------------------------------
extern "C" void kernel_launch(void* const* d_in, const int* in_sizes, int n_in,
                              void* d_out, int out_size)
{
    const float* q0     = (const float*)d_in[0];
    const float* q1     = (const float*)d_in[1];
    const float* ref    = (const float*)d_in[2];
    const float* flat0  = (const float*)d_in[3];
    const float* flat1  = (const float*)d_in[4];
    const int*   shapes = (const int*)  d_in[5];
    const int*   starts = (const int*)  d_in[6];
    const float* W_so   = (const float*)d_in[7];
    const float* b_so   = (const float*)d_in[8];
    const float* W_aw   = (const float*)d_in[9];
    const float* b_aw   = (const float*)d_in[10];
    const float* W_v    = (const float*)d_in[11];
    const float* b_v    = (const float*)d_in[12];
    const float* W_o    = (const float*)d_in[13];
    const float* b_o    = (const float*)d_in[14];
    const float* W_agg  = (const float*)d_in[15];
    const float* b_agg  = (const float*)d_in[16];
    float* out = (float*)d_out;

    __half *value0, *value1, *Whv, *Whso, *Whaw, *Whf0, *Whf1;
    float *off0, *off1, *aw0, *aw1, *dd0, *dd1, *bf;
    cudaGetSymbolAddress((void**)&value0, g_value0);
    cudaGetSymbolAddress((void**)&value1, g_value1);
    cudaGetSymbolAddress((void**)&off0, g_off0);
    cudaGetSymbolAddress((void**)&off1, g_off1);
    cudaGetSymbolAddress((void**)&aw0, g_aw0);
    cudaGetSymbolAddress((void**)&aw1, g_aw1);
    cudaGetSymbolAddress((void**)&dd0, g_d0);
    cudaGetSymbolAddress((void**)&dd1, g_d1);
    cudaGetSymbolAddress((void**)&Whv, g_Whv);
    cudaGetSymbolAddress((void**)&Whso, g_Whso);
    cudaGetSymbolAddress((void**)&Whaw, g_Whaw);
    cudaGetSymbolAddress((void**)&Whf0, g_Whf0);
    cudaGetSymbolAddress((void**)&Whf1, g_Whf1);
    cudaGetSymbolAddress((void**)&bf, g_bf);

    dim3 blk(256);
    const int MT = (NROWS + 127) / 128;   // 306

    // --- fused weight prep: 3 launches (was 8) ---
    transpose_batch_kernel<<<dim3(8, 8, 3), dim3(32, 8)>>>(W_v, W_so, W_aw,
                                                           Whv, Whso, Whaw);  // 1
    wfprep_kernel<<<dim3(16, 2), blk>>>(W_o, W_agg, Whf0, Whf1);              // 2
    fuse_bias_kernel<<<1, DMODEL>>>(b_o, b_agg, W_agg, bf);                   // 3

    // --- big projections (launches 4-9; #5/#6 are big HMMA for profiling) ---
    gemm_hmma<256, 1><<<dim3(4, MT), blk>>>(flat0, flat0, 4, Whv, Whv, 4, b_v, value0, NROWS); // 4
    gemm_hmma<256, 1><<<dim3(4, MT), blk>>>(flat1, flat1, 4, Whv, Whv, 4, b_v, value1, NROWS); // 5
    gemm_hmma<256, 0><<<dim3(4, MT), blk>>>(q0, q0, 4, Whso, Whso, 4, b_so, off0, NROWS);      // 6
    gemm_hmma<256, 0><<<dim3(4, MT), blk>>>(q1, q1, 4, Whso, Whso, 4, b_so, off1, NROWS);      // 7
    gemm_hmma<128, 0><<<dim3(2, MT), blk>>>(q0, q0, 4, Whaw, Whaw, 4, b_aw, aw0, NROWS);       // 8
    gemm_hmma<128, 0><<<dim3(2, MT), blk>>>(q1, q1, 4, Whaw, Whaw, 4, b_aw, aw1, NROWS);       // 9

    // --- joint softmax over 32 ---
    {
        int total = NROWS * NHEADS;
        softmax_kernel<<<(total + 255) / 256, 256>>>(aw0, aw1, total);
    }

    // --- deformable sampling ---
    {
        int warps = NROWS * NHEADS;
        int blocks = (warps * 32 + 255) / 256;
        sample_kernel<<<blocks, 256>>>(value0, ref, off0, aw0, shapes, starts, dd0);
        sample_kernel<<<blocks, 256>>>(value1, ref, off1, aw1, shapes, starts, dd1);
    }

    // --- fused output projection: out = d0@Whf0^T + d1@Whf1^T + bf (K=512) ---
    gemm_hmma<256, 0><<<dim3(4, MT), blk>>>(dd0, dd1, 4, Whf0, Whf1, 8, bf, out, NROWS);

    (void)in_sizes; (void)n_in; (void)out_size;
}

// round 12
// speedup vs baseline: 1.6270x; 1.4406x over previous
#include <cuda_runtime.h>
#include <cuda_fp16.h>
#include <mma.h>
#include <cstdint>

using namespace nvcuda;

// ---------------------------------------------------------------------------
// Problem constants
// ---------------------------------------------------------------------------
#define NB      2
#define LQ      19560
#define DMODEL  256
#define NHEADS  8
#define NLEV    4
#define NPTS    4
#define HDIM    32
#define NROWS   (NB * LQ)   // 39120
#define KSTRIDE 256

// FPN level shapes (fixed by the problem definition)
__device__ __constant__ const int LVL_H[4] = {92, 46, 23, 12};
__device__ __constant__ const int LVL_W[4] = {160, 80, 40, 20};
__device__ __constant__ const int LVL_S[4] = {0, 14720, 18400, 19320};

// ---------------------------------------------------------------------------
// Device scratch (static; no cudaMalloc allowed)
// ---------------------------------------------------------------------------
__device__ __align__(256) __half g_value0[NROWS * DMODEL];
__device__ __align__(256) __half g_value1[NROWS * DMODEL];
__device__ __align__(256) float  g_off0[NROWS * DMODEL];
__device__ __align__(256) float  g_off1[NROWS * DMODEL];
__device__ __align__(256) float  g_aw0[NROWS * 128];
__device__ __align__(256) float  g_aw1[NROWS * 128];
__device__ __align__(256) float  g_d0[NROWS * DMODEL];
__device__ __align__(256) float  g_d1[NROWS * DMODEL];
__device__ __align__(256) __half g_Whv[DMODEL * DMODEL];     // half, K-major
__device__ __align__(256) __half g_Whso[DMODEL * DMODEL];
__device__ __align__(256) __half g_Whaw[128 * DMODEL];
__device__ __align__(256) __half g_Whf0[DMODEL * DMODEL];    // (W_o@W_aggT)^T half
__device__ __align__(256) __half g_Whf1[DMODEL * DMODEL];
__device__ __align__(256) float  g_bf[DMODEL];

// ---------------------------------------------------------------------------
// Batched transpose fp32 -> half, K-major. blockIdx.z selects matrix.
// ---------------------------------------------------------------------------
__global__ void transpose_batch_kernel(
    const float* __restrict__ W_v, const float* __restrict__ W_so,
    const float* __restrict__ W_aw,
    __half* __restrict__ Whv, __half* __restrict__ Whso, __half* __restrict__ Whaw)
{
    const float* in; __half* out; int C;
    if (blockIdx.z == 0)      { in = W_v;  out = Whv;  C = 256; }
    else if (blockIdx.z == 1) { in = W_so; out = Whso; C = 256; }
    else                      { in = W_aw; out = Whaw; C = 128; }
    const int R = 256;

    __shared__ float t[32][33];
    int bx = blockIdx.x * 32, by = blockIdx.y * 32;
    int x = bx + threadIdx.x;
#pragma unroll
    for (int i = 0; i < 32; i += 8) {
        int y = by + threadIdx.y + i;
        if (x < C && y < R) t[threadIdx.y + i][threadIdx.x] = in[(size_t)y * C + x];
    }
    __syncthreads();
    int x2 = by + threadIdx.x;
#pragma unroll
    for (int i = 0; i < 32; i += 8) {
        int y2 = bx + threadIdx.y + i;
        if (x2 < R && y2 < C) out[(size_t)y2 * R + x2] = __float2half(t[threadIdx.x][threadIdx.y + i]);
    }
}

// ---------------------------------------------------------------------------
// wfprep: Whf_i[j][m] = half( sum_k W_o[m][k] * W_agg_i[k][j] )
// ---------------------------------------------------------------------------
__global__ __launch_bounds__(256) void wfprep_kernel(
    const float* __restrict__ W_o, const float* __restrict__ W_agg,
    __half* __restrict__ Whf0, __half* __restrict__ Whf1)
{
    __shared__ float sA[16][256];
    const float* Wagg = W_agg + (size_t)blockIdx.y * 256 * 256;
    __half* Whf = blockIdx.y ? Whf1 : Whf0;
    const int m0 = blockIdx.x * 16;
    const int tid = threadIdx.x;

    for (int i = tid; i < 16 * 256; i += 256)
        sA[i >> 8][i & 255] = W_o[(size_t)(m0 + (i >> 8)) * 256 + (i & 255)];
    __syncthreads();

    const int j = tid;
    float acc[16];
#pragma unroll
    for (int m = 0; m < 16; m++) acc[m] = 0.f;
    for (int k = 0; k < 256; k++) {
        float b = Wagg[(size_t)k * 256 + j];
#pragma unroll
        for (int m = 0; m < 16; m++) acc[m] = fmaf(sA[m][k], b, acc[m]);
    }
#pragma unroll
    for (int m = 0; m < 16; m++)
        Whf[(size_t)j * 256 + m0 + m] = __float2half(acc[m]);
}

// ---------------------------------------------------------------------------
// bf[j] = b_agg[j] + sum_m b_o[m] * (W_agg[m][j] + W_agg[m+256][j])
// ---------------------------------------------------------------------------
__global__ void fuse_bias_kernel(const float* __restrict__ b_o,
                                 const float* __restrict__ b_agg,
                                 const float* __restrict__ W_agg,
                                 float* __restrict__ bf)
{
    int j = threadIdx.x;
    float s = b_agg[j];
    for (int m = 0; m < DMODEL; m++)
        s += b_o[m] * (W_agg[(size_t)m * DMODEL + j] +
                       W_agg[(size_t)(m + DMODEL) * DMODEL + j]);
    bf[j] = s;
}

// ---------------------------------------------------------------------------
// fp16 wmma GEMM (m16n16k16, fp32 accum).  (R7/R10-proven)
// ---------------------------------------------------------------------------
template <int NT, int EPI>
__global__ __launch_bounds__(256) void gemm_hmma(
    const float* __restrict__ A0, const float* __restrict__ A1, int chunksA,
    const __half* __restrict__ B0, const __half* __restrict__ B1, int chunksTot,
    const float* __restrict__ bias, void* __restrict__ Cout, int M)
{
    __shared__ __align__(128) union {
        struct { __half A[128][72]; __half B[64][72]; } ld;  // 27648 B
        float C[128][72];                                    // 36864 B
    } sm;

    const int tid = threadIdx.x;
    const int wid = tid >> 5;
    const int wm = (wid & 3) * 32;
    const int wn = (wid >> 2) * 32;
    const int mbase = blockIdx.y * 128;
    const int ncol0 = blockIdx.x * 64;

    wmma::fragment<wmma::accumulator, 16, 16, 16, float> acc[2][2];
#pragma unroll
    for (int i = 0; i < 2; i++)
#pragma unroll
        for (int j = 0; j < 2; j++) wmma::fill_fragment(acc[i][j], 0.f);

    for (int c = 0; c < chunksTot; ++c) {
        const float* Ap; const __half* Bp; int kloc;
        if (c < chunksA) { Ap = A0; Bp = B0; kloc = c * 64; }
        else             { Ap = A1; Bp = B1; kloc = (c - chunksA) * 64; }

#pragma unroll
        for (int i = tid; i < 2048; i += 256) {
            const int row = i >> 4, j = i & 15;
            const int grow = mbase + row;
            float4 v = make_float4(0.f, 0.f, 0.f, 0.f);
            if (grow < M) v = *(const float4*)&Ap[(size_t)grow * KSTRIDE + kloc + j * 4];
            *(__half2*)&sm.ld.A[row][j * 4]     = __floats2half2_rn(v.x, v.y);
            *(__half2*)&sm.ld.A[row][j * 4 + 2] = __floats2half2_rn(v.z, v.w);
        }
#pragma unroll
        for (int i = tid; i < 512; i += 256) {
            const int row = i >> 3, j = i & 7;
            int4 v = *(const int4*)&Bp[(size_t)(ncol0 + row) * KSTRIDE + kloc + j * 8];
            *(int4*)&sm.ld.B[row][j * 8] = v;
        }
        __syncthreads();

#pragma unroll
        for (int kk = 0; kk < 64; kk += 16) {
            wmma::fragment<wmma::matrix_a, 16, 16, 16, __half, wmma::row_major> a0, a1;
            wmma::fragment<wmma::matrix_b, 16, 16, 16, __half, wmma::col_major> b0, b1;
            wmma::load_matrix_sync(a0, &sm.ld.A[wm][kk], 72);
            wmma::load_matrix_sync(a1, &sm.ld.A[wm + 16][kk], 72);
            wmma::load_matrix_sync(b0, &sm.ld.B[wn][kk], 72);
            wmma::load_matrix_sync(b1, &sm.ld.B[wn + 16][kk], 72);
            wmma::mma_sync(acc[0][0], a0, b0, acc[0][0]);
            wmma::mma_sync(acc[0][1], a0, b1, acc[0][1]);
            wmma::mma_sync(acc[1][0], a1, b0, acc[1][0]);
            wmma::mma_sync(acc[1][1], a1, b1, acc[1][1]);
        }
        __syncthreads();
    }

    wmma::store_matrix_sync(&sm.C[wm][wn],           acc[0][0], 72, wmma::mem_row_major);
    wmma::store_matrix_sync(&sm.C[wm][wn + 16],      acc[0][1], 72, wmma::mem_row_major);
    wmma::store_matrix_sync(&sm.C[wm + 16][wn],      acc[1][0], 72, wmma::mem_row_major);
    wmma::store_matrix_sync(&sm.C[wm + 16][wn + 16], acc[1][1], 72, wmma::mem_row_major);
    __syncthreads();

#pragma unroll
    for (int i = tid; i < 128 * 16; i += 256) {
        const int row = i >> 4, j = i & 15;
        const int grow = mbase + row;
        if (grow < M) {
            const int col = ncol0 + j * 4;
            float4 v = *(const float4*)&sm.C[row][j * 4];
            if (bias) {
                v.x += bias[col + 0]; v.y += bias[col + 1];
                v.z += bias[col + 2]; v.w += bias[col + 3];
            }
            if (EPI == 0) {
                *(float4*)((float*)Cout + (size_t)grow * NT + col) = v;
            } else {
                __half* Cp = (__half*)Cout + (size_t)grow * NT + col;
                *(__half2*)(Cp)     = __floats2half2_rn(v.x, v.y);
                *(__half2*)(Cp + 2) = __floats2half2_rn(v.z, v.w);
            }
        }
    }
}

// ---------------------------------------------------------------------------
// Joint softmax over 32 = concat(aw0[16], aw1[16]) per (n,q,h); in-place.
// ---------------------------------------------------------------------------
__global__ void softmax_kernel(float* __restrict__ aw0, float* __restrict__ aw1,
                               int total)
{
    int t = blockIdx.x * blockDim.x + threadIdx.x;
    if (t >= total) return;
    float4* p0 = (float4*)(aw0 + (size_t)t * 16);
    float4* p1 = (float4*)(aw1 + (size_t)t * 16);
    float v[32];
    float4 r;
#pragma unroll
    for (int i = 0; i < 4; i++) {
        r = p0[i]; v[i*4+0]=r.x; v[i*4+1]=r.y; v[i*4+2]=r.z; v[i*4+3]=r.w;
    }
#pragma unroll
    for (int i = 0; i < 4; i++) {
        r = p1[i]; v[16+i*4+0]=r.x; v[16+i*4+1]=r.y; v[16+i*4+2]=r.z; v[16+i*4+3]=r.w;
    }
    float mx = v[0];
#pragma unroll
    for (int i = 1; i < 32; i++) mx = fmaxf(mx, v[i]);
    float sum = 0.f;
#pragma unroll
    for (int i = 0; i < 32; i++) { v[i] = expf(v[i] - mx); sum += v[i]; }
    float inv = 1.f / sum;
#pragma unroll
    for (int i = 0; i < 32; i++) v[i] *= inv;
#pragma unroll
    for (int i = 0; i < 4; i++)
        p0[i] = make_float4(v[i*4+0], v[i*4+1], v[i*4+2], v[i*4+3]);
#pragma unroll
    for (int i = 0; i < 4; i++)
        p1[i] = make_float4(v[16+i*4+0], v[16+i*4+1], v[16+i*4+2], v[16+i*4+3]);
}

// ---------------------------------------------------------------------------
// Deformable sampling, head-pair version (halves warp count + LDG/ALU/SHFL
// instruction count vs one-warp-per-head).  One warp = (n,q,head-pair);
// each half-warp = one head, 16 lanes x __half2 (2 channels/lane).
// Width-16 shuffles keep half-warps independent.
// ---------------------------------------------------------------------------
__global__ __launch_bounds__(256) void sample2_kernel(
    const __half* __restrict__ value, const float* __restrict__ ref,
    const float* __restrict__ off, const float* __restrict__ attn,
    float* __restrict__ out)
{
    const int gwarp = blockIdx.x * 8 + (threadIdx.x >> 5);
    const int lane = threadIdx.x & 31;
    if (gwarp >= NROWS * 4) return;

    const int hp = gwarp & 3;
    const int nq = gwarp >> 2;
    const int n = nq / LQ;
    const int h = hp * 2 + (lane >> 4);
    const int s = lane & 15;

    const float offA = off[((size_t)nq * NHEADS + h) * 32 + s];
    const float offB = off[((size_t)nq * NHEADS + h) * 32 + 16 + s];
    const float attv = attn[((size_t)nq * NHEADS + h) * 16 + s];
    const float refv = (s < 8) ? ref[(size_t)nq * 8 + s] : 0.f;

    float accx = 0.f, accy = 0.f;

#pragma unroll
    for (int l = 0; l < NLEV; l++) {
        const int H = LVL_H[l], W = LVL_W[l], st = LVL_S[l];
        const float fW = (float)W, fH = (float)H;
        const float rx = __shfl_sync(0xFFFFFFFFu, refv, l * 2 + 0, 16);
        const float ry = __shfl_sync(0xFFFFFFFFu, refv, l * 2 + 1, 16);
        const __half* vbase =
            value + (((size_t)n * LQ + st) * NHEADS + h) * HDIM + 2 * s;

#pragma unroll
        for (int p = 0; p < NPTS; p++) {
            const int sp = l * 4 + p;
            float ox, oy;
            if (sp < 8) {
                ox = __shfl_sync(0xFFFFFFFFu, offA, sp * 2 + 0, 16);
                oy = __shfl_sync(0xFFFFFFFFu, offA, sp * 2 + 1, 16);
            } else {
                ox = __shfl_sync(0xFFFFFFFFu, offB, sp * 2 - 16, 16);
                oy = __shfl_sync(0xFFFFFFFFu, offB, sp * 2 - 15, 16);
            }
            const float a = __shfl_sync(0xFFFFFFFFu, attv, sp, 16);

            // match reference arithmetic order exactly
            float x = (rx + ox / fW) * fW - 0.5f;
            float y = (ry + oy / fH) * fH - 0.5f;
            float x0f = floorf(x), y0f = floorf(y);
            int x0 = (int)x0f, y0 = (int)y0f;
            float lx = x - x0f, ly = y - y0f;
            float hx = 1.f - lx, hy = 1.f - ly;

            float smpx = 0.f, smpy = 0.f;
            const bool xin0 = (x0 >= 0) & (x0 < W);
            const bool xin1 = (x0 + 1 >= 0) & (x0 + 1 < W);
            const bool yin0 = (y0 >= 0) & (y0 < H);
            const bool yin1 = (y0 + 1 >= 0) & (y0 + 1 < H);
            if (xin0 & yin0) {
                float2 v = __half22float2(*(const __half2*)(vbase + (size_t)(y0 * W + x0) * DMODEL));
                float w = hy * hx; smpx = fmaf(w, v.x, smpx); smpy = fmaf(w, v.y, smpy);
            }
            if (xin1 & yin0) {
                float2 v = __half22float2(*(const __half2*)(vbase + (size_t)(y0 * W + x0 + 1) * DMODEL));
                float w = hy * lx; smpx = fmaf(w, v.x, smpx); smpy = fmaf(w, v.y, smpy);
            }
            if (xin0 & yin1) {
                float2 v = __half22float2(*(const __half2*)(vbase + (size_t)((y0 + 1) * W + x0) * DMODEL));
                float w = ly * hx; smpx = fmaf(w, v.x, smpx); smpy = fmaf(w, v.y, smpy);
            }
            if (xin1 & yin1) {
                float2 v = __half22float2(*(const __half2*)(vbase + (size_t)((y0 + 1) * W + x0 + 1) * DMODEL));
                float w = ly * lx; smpx = fmaf(w, v.x, smpx); smpy = fmaf(w, v.y, smpy);
            }
            accx = fmaf(a, smpx, accx);
            accy = fmaf(a, smpy, accy);
        }
    }

    *(float2*)&out[(size_t)nq * DMODEL + h * HDIM + 2 * s] = make_float2(accx, accy);
}

// ---------------------------------------------------------------------------
// Launcher
// ---------------------------------------------------------------------------
extern "C" void kernel_launch(void* const* d_in, const int* in_sizes, int n_in,
                              void* d_out, int out_size)
{
    const float* q0     = (const float*)d_in[0];
    const float* q1     = (const float*)d_in[1];
    const float* ref    = (const float*)d_in[2];
    const float* flat0  = (const float*)d_in[3];
    const float* flat1  = (const float*)d_in[4];
    const float* W_so   = (const float*)d_in[7];
    const float* b_so   = (const float*)d_in[8];
    const float* W_aw   = (const float*)d_in[9];
    const float* b_aw   = (const float*)d_in[10];
    const float* W_v    = (const float*)d_in[11];
    const float* b_v    = (const float*)d_in[12];
    const float* W_o    = (const float*)d_in[13];
    const float* b_o    = (const float*)d_in[14];
    const float* W_agg  = (const float*)d_in[15];
    const float* b_agg  = (const float*)d_in[16];
    float* out = (float*)d_out;

    __half *value0, *value1, *Whv, *Whso, *Whaw, *Whf0, *Whf1;
    float *off0, *off1, *aw0, *aw1, *dd0, *dd1, *bf;
    cudaGetSymbolAddress((void**)&value0, g_value0);
    cudaGetSymbolAddress((void**)&value1, g_value1);
    cudaGetSymbolAddress((void**)&off0, g_off0);
    cudaGetSymbolAddress((void**)&off1, g_off1);
    cudaGetSymbolAddress((void**)&aw0, g_aw0);
    cudaGetSymbolAddress((void**)&aw1, g_aw1);
    cudaGetSymbolAddress((void**)&dd0, g_d0);
    cudaGetSymbolAddress((void**)&dd1, g_d1);
    cudaGetSymbolAddress((void**)&Whv, g_Whv);
    cudaGetSymbolAddress((void**)&Whso, g_Whso);
    cudaGetSymbolAddress((void**)&Whaw, g_Whaw);
    cudaGetSymbolAddress((void**)&Whf0, g_Whf0);
    cudaGetSymbolAddress((void**)&Whf1, g_Whf1);
    cudaGetSymbolAddress((void**)&bf, g_bf);

    dim3 blk(256);
    const int MT = (NROWS + 127) / 128;   // 306

    // --- fused weight prep: 3 launches ---
    transpose_batch_kernel<<<dim3(8, 8, 3), dim3(32, 8)>>>(W_v, W_so, W_aw,
                                                           Whv, Whso, Whaw);
    wfprep_kernel<<<dim3(16, 2), blk>>>(W_o, W_agg, Whf0, Whf1);
    fuse_bias_kernel<<<1, DMODEL>>>(b_o, b_agg, W_agg, bf);

    // --- big projections ---
    gemm_hmma<256, 1><<<dim3(4, MT), blk>>>(flat0, flat0, 4, Whv, Whv, 4, b_v, value0, NROWS);
    gemm_hmma<256, 1><<<dim3(4, MT), blk>>>(flat1, flat1, 4, Whv, Whv, 4, b_v, value1, NROWS);
    gemm_hmma<256, 0><<<dim3(4, MT), blk>>>(q0, q0, 4, Whso, Whso, 4, b_so, off0, NROWS);
    gemm_hmma<256, 0><<<dim3(4, MT), blk>>>(q1, q1, 4, Whso, Whso, 4, b_so, off1, NROWS);
    gemm_hmma<128, 0><<<dim3(2, MT), blk>>>(q0, q0, 4, Whaw, Whaw, 4, b_aw, aw0, NROWS);
    gemm_hmma<128, 0><<<dim3(2, MT), blk>>>(q1, q1, 4, Whaw, Whaw, 4, b_aw, aw1, NROWS);

    // --- joint softmax over 32 ---
    {
        int total = NROWS * NHEADS;
        softmax_kernel<<<(total + 255) / 256, 256>>>(aw0, aw1, total);
    }

    // --- deformable sampling: head-pair warps (half the instructions) ---
    {
        int blocks = (NROWS * 4 + 7) / 8;   // 19560
        sample2_kernel<<<blocks, 256>>>(value0, ref, off0, aw0, dd0);
        sample2_kernel<<<blocks, 256>>>(value1, ref, off1, aw1, dd1);
    }

    // --- fused output projection: out = d0@Whf0^T + d1@Whf1^T + bf (K=512) ---
    gemm_hmma<256, 0><<<dim3(4, MT), blk>>>(dd0, dd1, 4, Whf0, Whf1, 8, bf, out, NROWS);

    (void)in_sizes; (void)n_in; (void)out_size;
}

// round 14
// speedup vs baseline: 2.0178x; 1.2401x over previous
#include <cuda_runtime.h>
#include <cuda_fp16.h>
#include <mma.h>
#include <cstdint>

using namespace nvcuda;

// ---------------------------------------------------------------------------
// Problem constants
// ---------------------------------------------------------------------------
#define NB      2
#define LQ      19560
#define DMODEL  256
#define NHEADS  8
#define NLEV    4
#define NPTS    4
#define HDIM    32
#define NROWS   (NB * LQ)   // 39120
#define KSTRIDE 256

// FPN level shapes (fixed by the problem definition)
__device__ __constant__ const int LVL_H[4] = {92, 46, 23, 12};
__device__ __constant__ const int LVL_W[4] = {160, 80, 40, 20};
__device__ __constant__ const int LVL_S[4] = {0, 14720, 18400, 19320};

// ---------------------------------------------------------------------------
// Device scratch (static; no cudaMalloc allowed)
// ---------------------------------------------------------------------------
__device__ __align__(256) __half g_value0[NROWS * DMODEL];
__device__ __align__(256) __half g_value1[NROWS * DMODEL];
__device__ __align__(256) float  g_off0[NROWS * DMODEL];
__device__ __align__(256) float  g_off1[NROWS * DMODEL];
__device__ __align__(256) float  g_aw0[NROWS * 128];
__device__ __align__(256) float  g_aw1[NROWS * 128];
__device__ __align__(256) float  g_d0[NROWS * DMODEL];
__device__ __align__(256) float  g_d1[NROWS * DMODEL];
__device__ __align__(256) __half g_Whv[DMODEL * DMODEL];     // half, K-major
__device__ __align__(256) __half g_Whso[DMODEL * DMODEL];
__device__ __align__(256) __half g_Whaw[128 * DMODEL];
__device__ __align__(256) __half g_Whf0[DMODEL * DMODEL];    // (W_o@W_aggT)^T half
__device__ __align__(256) __half g_Whf1[DMODEL * DMODEL];
__device__ __align__(256) float  g_bf[DMODEL];

// ---------------------------------------------------------------------------
// Batched transpose fp32 -> half, K-major. blockIdx.z selects matrix.
// ---------------------------------------------------------------------------
__global__ void transpose_batch_kernel(
    const float* __restrict__ W_v, const float* __restrict__ W_so,
    const float* __restrict__ W_aw,
    __half* __restrict__ Whv, __half* __restrict__ Whso, __half* __restrict__ Whaw)
{
    const float* in; __half* out; int C;
    if (blockIdx.z == 0)      { in = W_v;  out = Whv;  C = 256; }
    else if (blockIdx.z == 1) { in = W_so; out = Whso; C = 256; }
    else                      { in = W_aw; out = Whaw; C = 128; }
    const int R = 256;

    __shared__ float t[32][33];
    int bx = blockIdx.x * 32, by = blockIdx.y * 32;
    int x = bx + threadIdx.x;
#pragma unroll
    for (int i = 0; i < 32; i += 8) {
        int y = by + threadIdx.y + i;
        if (x < C && y < R) t[threadIdx.y + i][threadIdx.x] = in[(size_t)y * C + x];
    }
    __syncthreads();
    int x2 = by + threadIdx.x;
#pragma unroll
    for (int i = 0; i < 32; i += 8) {
        int y2 = bx + threadIdx.y + i;
        if (x2 < R && y2 < C) out[(size_t)y2 * R + x2] = __float2half(t[threadIdx.x][threadIdx.y + i]);
    }
}

// ---------------------------------------------------------------------------
// wfprep: Whf_i[j][m] = half( sum_k W_o[m][k] * W_agg_i[k][j] )
// ---------------------------------------------------------------------------
__global__ __launch_bounds__(256) void wfprep_kernel(
    const float* __restrict__ W_o, const float* __restrict__ W_agg,
    __half* __restrict__ Whf0, __half* __restrict__ Whf1)
{
    __shared__ float sA[16][256];
    const float* Wagg = W_agg + (size_t)blockIdx.y * 256 * 256;
    __half* Whf = blockIdx.y ? Whf1 : Whf0;
    const int m0 = blockIdx.x * 16;
    const int tid = threadIdx.x;

    for (int i = tid; i < 16 * 256; i += 256)
        sA[i >> 8][i & 255] = W_o[(size_t)(m0 + (i >> 8)) * 256 + (i & 255)];
    __syncthreads();

    const int j = tid;
    float acc[16];
#pragma unroll
    for (int m = 0; m < 16; m++) acc[m] = 0.f;
    for (int k = 0; k < 256; k++) {
        float b = Wagg[(size_t)k * 256 + j];
#pragma unroll
        for (int m = 0; m < 16; m++) acc[m] = fmaf(sA[m][k], b, acc[m]);
    }
#pragma unroll
    for (int m = 0; m < 16; m++)
        Whf[(size_t)j * 256 + m0 + m] = __float2half(acc[m]);
}

// ---------------------------------------------------------------------------
// bf[j] = b_agg[j] + sum_m b_o[m] * (W_agg[m][j] + W_agg[m+256][j])
// ---------------------------------------------------------------------------
__global__ void fuse_bias_kernel(const float* __restrict__ b_o,
                                 const float* __restrict__ b_agg,
                                 const float* __restrict__ W_agg,
                                 float* __restrict__ bf)
{
    int j = threadIdx.x;
    float s = b_agg[j];
    for (int m = 0; m < DMODEL; m++)
        s += b_o[m] * (W_agg[(size_t)m * DMODEL + j] +
                       W_agg[(size_t)(m + DMODEL) * DMODEL + j]);
    bf[j] = s;
}

// ---------------------------------------------------------------------------
// fp16 wmma GEMM (m16n16k16, fp32 accum).  (R7/R10/R12-proven)
// ---------------------------------------------------------------------------
template <int NT, int EPI>
__global__ __launch_bounds__(256) void gemm_hmma(
    const float* __restrict__ A0, const float* __restrict__ A1, int chunksA,
    const __half* __restrict__ B0, const __half* __restrict__ B1, int chunksTot,
    const float* __restrict__ bias, void* __restrict__ Cout, int M)
{
    __shared__ __align__(128) union {
        struct { __half A[128][72]; __half B[64][72]; } ld;  // 27648 B
        float C[128][72];                                    // 36864 B
    } sm;

    const int tid = threadIdx.x;
    const int wid = tid >> 5;
    const int wm = (wid & 3) * 32;
    const int wn = (wid >> 2) * 32;
    const int mbase = blockIdx.y * 128;
    const int ncol0 = blockIdx.x * 64;

    wmma::fragment<wmma::accumulator, 16, 16, 16, float> acc[2][2];
#pragma unroll
    for (int i = 0; i < 2; i++)
#pragma unroll
        for (int j = 0; j < 2; j++) wmma::fill_fragment(acc[i][j], 0.f);

    for (int c = 0; c < chunksTot; ++c) {
        const float* Ap; const __half* Bp; int kloc;
        if (c < chunksA) { Ap = A0; Bp = B0; kloc = c * 64; }
        else             { Ap = A1; Bp = B1; kloc = (c - chunksA) * 64; }

#pragma unroll
        for (int i = tid; i < 2048; i += 256) {
            const int row = i >> 4, j = i & 15;
            const int grow = mbase + row;
            float4 v = make_float4(0.f, 0.f, 0.f, 0.f);
            if (grow < M) v = *(const float4*)&Ap[(size_t)grow * KSTRIDE + kloc + j * 4];
            *(__half2*)&sm.ld.A[row][j * 4]     = __floats2half2_rn(v.x, v.y);
            *(__half2*)&sm.ld.A[row][j * 4 + 2] = __floats2half2_rn(v.z, v.w);
        }
#pragma unroll
        for (int i = tid; i < 512; i += 256) {
            const int row = i >> 3, j = i & 7;
            int4 v = *(const int4*)&Bp[(size_t)(ncol0 + row) * KSTRIDE + kloc + j * 8];
            *(int4*)&sm.ld.B[row][j * 8] = v;
        }
        __syncthreads();

#pragma unroll
        for (int kk = 0; kk < 64; kk += 16) {
            wmma::fragment<wmma::matrix_a, 16, 16, 16, __half, wmma::row_major> a0, a1;
            wmma::fragment<wmma::matrix_b, 16, 16, 16, __half, wmma::col_major> b0, b1;
            wmma::load_matrix_sync(a0, &sm.ld.A[wm][kk], 72);
            wmma::load_matrix_sync(a1, &sm.ld.A[wm + 16][kk], 72);
            wmma::load_matrix_sync(b0, &sm.ld.B[wn][kk], 72);
            wmma::load_matrix_sync(b1, &sm.ld.B[wn + 16][kk], 72);
            wmma::mma_sync(acc[0][0], a0, b0, acc[0][0]);
            wmma::mma_sync(acc[0][1], a0, b1, acc[0][1]);
            wmma::mma_sync(acc[1][0], a1, b0, acc[1][0]);
            wmma::mma_sync(acc[1][1], a1, b1, acc[1][1]);
        }
        __syncthreads();
    }

    wmma::store_matrix_sync(&sm.C[wm][wn],           acc[0][0], 72, wmma::mem_row_major);
    wmma::store_matrix_sync(&sm.C[wm][wn + 16],      acc[0][1], 72, wmma::mem_row_major);
    wmma::store_matrix_sync(&sm.C[wm + 16][wn],      acc[1][0], 72, wmma::mem_row_major);
    wmma::store_matrix_sync(&sm.C[wm + 16][wn + 16], acc[1][1], 72, wmma::mem_row_major);
    __syncthreads();

#pragma unroll
    for (int i = tid; i < 128 * 16; i += 256) {
        const int row = i >> 4, j = i & 15;
        const int grow = mbase + row;
        if (grow < M) {
            const int col = ncol0 + j * 4;
            float4 v = *(const float4*)&sm.C[row][j * 4];
            if (bias) {
                v.x += bias[col + 0]; v.y += bias[col + 1];
                v.z += bias[col + 2]; v.w += bias[col + 3];
            }
            if (EPI == 0) {
                *(float4*)((float*)Cout + (size_t)grow * NT + col) = v;
            } else {
                __half* Cp = (__half*)Cout + (size_t)grow * NT + col;
                *(__half2*)(Cp)     = __floats2half2_rn(v.x, v.y);
                *(__half2*)(Cp + 2) = __floats2half2_rn(v.z, v.w);
            }
        }
    }
}

// ---------------------------------------------------------------------------
// Joint softmax over 32 = concat(aw0[16], aw1[16]) per (n,q,h); in-place.
// ---------------------------------------------------------------------------
__global__ void softmax_kernel(float* __restrict__ aw0, float* __restrict__ aw1,
                               int total)
{
    int t = blockIdx.x * blockDim.x + threadIdx.x;
    if (t >= total) return;
    float4* p0 = (float4*)(aw0 + (size_t)t * 16);
    float4* p1 = (float4*)(aw1 + (size_t)t * 16);
    float v[32];
    float4 r;
#pragma unroll
    for (int i = 0; i < 4; i++) {
        r = p0[i]; v[i*4+0]=r.x; v[i*4+1]=r.y; v[i*4+2]=r.z; v[i*4+3]=r.w;
    }
#pragma unroll
    for (int i = 0; i < 4; i++) {
        r = p1[i]; v[16+i*4+0]=r.x; v[16+i*4+1]=r.y; v[16+i*4+2]=r.z; v[16+i*4+3]=r.w;
    }
    float mx = v[0];
#pragma unroll
    for (int i = 1; i < 32; i++) mx = fmaxf(mx, v[i]);
    float sum = 0.f;
#pragma unroll
    for (int i = 0; i < 32; i++) { v[i] = expf(v[i] - mx); sum += v[i]; }
    float inv = 1.f / sum;
#pragma unroll
    for (int i = 0; i < 32; i++) v[i] *= inv;
#pragma unroll
    for (int i = 0; i < 4; i++)
        p0[i] = make_float4(v[i*4+0], v[i*4+1], v[i*4+2], v[i*4+3]);
#pragma unroll
    for (int i = 0; i < 4; i++)
        p1[i] = make_float4(v[16+i*4+0], v[16+i*4+1], v[16+i*4+2], v[16+i*4+3]);
}

// ---------------------------------------------------------------------------
// Deformable sampling, head-quad version.
//   One warp = (n,q,head-quad); each 8-lane group = one head, lane = 4
//   channels via one 8-byte gather per corner.  Width-8 shuffles.
//   blockIdx.y = iter.
// ---------------------------------------------------------------------------
__global__ __launch_bounds__(256) void sample4_kernel(
    const __half* __restrict__ v0, const __half* __restrict__ v1,
    const float* __restrict__ ref,
    const float* __restrict__ o0, const float* __restrict__ o1,
    const float* __restrict__ a0, const float* __restrict__ a1,
    float* __restrict__ d0, float* __restrict__ d1)
{
    const int iter = blockIdx.y;
    const __half* value = iter ? v1 : v0;
    const float* off    = iter ? o1 : o0;
    const float* attn   = iter ? a1 : a0;
    float* out          = iter ? d1 : d0;

    const int gwarp = blockIdx.x * 8 + (threadIdx.x >> 5);
    const int lane = threadIdx.x & 31;
    if (gwarp >= NROWS * 2) return;

    const int hq = gwarp & 1;            // head quad: heads 0-3 or 4-7
    const int nq = gwarp >> 1;
    const int n = nq / LQ;
    const int h = hq * 4 + (lane >> 3);
    const int s = lane & 7;              // 0..7 within head group

    // per-head metadata, distributed over the 8 lanes of this group
    const size_t ob = ((size_t)nq * NHEADS + h) * 32;
    const float of0 = off[ob + s];
    const float of1 = off[ob + 8 + s];
    const float of2 = off[ob + 16 + s];
    const float of3 = off[ob + 24 + s];
    const size_t ab = ((size_t)nq * NHEADS + h) * 16;
    const float at0 = attn[ab + s];
    const float at1 = attn[ab + 8 + s];
    const float refv = ref[(size_t)nq * 8 + s];

    float acc0 = 0.f, acc1 = 0.f, acc2 = 0.f, acc3 = 0.f;

#pragma unroll
    for (int l = 0; l < NLEV; l++) {
        const int H = LVL_H[l], W = LVL_W[l], st = LVL_S[l];
        const float fW = (float)W, fH = (float)H;
        const float rx = __shfl_sync(0xFFFFFFFFu, refv, l * 2 + 0, 8);
        const float ry = __shfl_sync(0xFFFFFFFFu, refv, l * 2 + 1, 8);
        const __half* vbase =
            value + (((size_t)n * LQ + st) * NHEADS + h) * HDIM + 4 * s;

#pragma unroll
        for (int p = 0; p < NPTS; p++) {
            const int sp = l * 4 + p;
            const int xi = 2 * sp, yi = 2 * sp + 1;
            // compile-time register selection (loop fully unrolled)
            const float oxs = (xi < 8) ? of0 : (xi < 16) ? of1 : (xi < 24) ? of2 : of3;
            const float oys = (yi < 8) ? of0 : (yi < 16) ? of1 : (yi < 24) ? of2 : of3;
            const float ox = __shfl_sync(0xFFFFFFFFu, oxs, xi & 7, 8);
            const float oy = __shfl_sync(0xFFFFFFFFu, oys, yi & 7, 8);
            const float a  = __shfl_sync(0xFFFFFFFFu, (sp < 8) ? at0 : at1, sp & 7, 8);

            // match reference arithmetic order exactly
            float x = (rx + ox / fW) * fW - 0.5f;
            float y = (ry + oy / fH) * fH - 0.5f;
            float x0f = floorf(x), y0f = floorf(y);
            int x0 = (int)x0f, y0 = (int)y0f;
            float lx = x - x0f, ly = y - y0f;
            float hx = 1.f - lx, hy = 1.f - ly;

            float s0 = 0.f, s1 = 0.f, s2 = 0.f, s3 = 0.f;
            const bool xin0 = (x0 >= 0) & (x0 < W);
            const bool xin1 = (x0 + 1 >= 0) & (x0 + 1 < W);
            const bool yin0 = (y0 >= 0) & (y0 < H);
            const bool yin1 = (y0 + 1 >= 0) & (y0 + 1 < H);
            if (xin0 & yin0) {
                uint2 u = *(const uint2*)(vbase + (size_t)(y0 * W + x0) * DMODEL);
                float2 va = __half22float2(*(__half2*)&u.x);
                float2 vb = __half22float2(*(__half2*)&u.y);
                float w = hy * hx;
                s0 = fmaf(w, va.x, s0); s1 = fmaf(w, va.y, s1);
                s2 = fmaf(w, vb.x, s2); s3 = fmaf(w, vb.y, s3);
            }
            if (xin1 & yin0) {
                uint2 u = *(const uint2*)(vbase + (size_t)(y0 * W + x0 + 1) * DMODEL);
                float2 va = __half22float2(*(__half2*)&u.x);
                float2 vb = __half22float2(*(__half2*)&u.y);
                float w = hy * lx;
                s0 = fmaf(w, va.x, s0); s1 = fmaf(w, va.y, s1);
                s2 = fmaf(w, vb.x, s2); s3 = fmaf(w, vb.y, s3);
            }
            if (xin0 & yin1) {
                uint2 u = *(const uint2*)(vbase + (size_t)((y0 + 1) * W + x0) * DMODEL);
                float2 va = __half22float2(*(__half2*)&u.x);
                float2 vb = __half22float2(*(__half2*)&u.y);
                float w = ly * hx;
                s0 = fmaf(w, va.x, s0); s1 = fmaf(w, va.y, s1);
                s2 = fmaf(w, vb.x, s2); s3 = fmaf(w, vb.y, s3);
            }
            if (xin1 & yin1) {
                uint2 u = *(const uint2*)(vbase + (size_t)((y0 + 1) * W + x0 + 1) * DMODEL);
                float2 va = __half22float2(*(__half2*)&u.x);
                float2 vb = __half22float2(*(__half2*)&u.y);
                float w = ly * lx;
                s0 = fmaf(w, va.x, s0); s1 = fmaf(w, va.y, s1);
                s2 = fmaf(w, vb.x, s2); s3 = fmaf(w, vb.y, s3);
            }
            acc0 = fmaf(a, s0, acc0);
            acc1 = fmaf(a, s1, acc1);
            acc2 = fmaf(a, s2, acc2);
            acc3 = fmaf(a, s3, acc3);
        }
    }

    *(float4*)&out[(size_t)nq * DMODEL + h * HDIM + 4 * s] =
        make_float4(acc0, acc1, acc2, acc3);
}

// ---------------------------------------------------------------------------
// Launcher
// ---------------------------------------------------------------------------
extern "C" void kernel_launch(void* const* d_in, const int* in_sizes, int n_in,
                              void* d_out, int out_size)
{
    const float* q0     = (const float*)d_in[0];
    const float* q1     = (const float*)d_in[1];
    const float* ref    = (const float*)d_in[2];
    const float* flat0  = (const float*)d_in[3];
    const float* flat1  = (const float*)d_in[4];
    const float* W_so   = (const float*)d_in[7];
    const float* b_so   = (const float*)d_in[8];
    const float* W_aw   = (const float*)d_in[9];
    const float* b_aw   = (const float*)d_in[10];
    const float* W_v    = (const float*)d_in[11];
    const float* b_v    = (const float*)d_in[12];
    const float* W_o    = (const float*)d_in[13];
    const float* b_o    = (const float*)d_in[14];
    const float* W_agg  = (const float*)d_in[15];
    const float* b_agg  = (const float*)d_in[16];
    float* out = (float*)d_out;

    __half *value0, *value1, *Whv, *Whso, *Whaw, *Whf0, *Whf1;
    float *off0, *off1, *aw0, *aw1, *dd0, *dd1, *bf;
    cudaGetSymbolAddress((void**)&value0, g_value0);
    cudaGetSymbolAddress((void**)&value1, g_value1);
    cudaGetSymbolAddress((void**)&off0, g_off0);
    cudaGetSymbolAddress((void**)&off1, g_off1);
    cudaGetSymbolAddress((void**)&aw0, g_aw0);
    cudaGetSymbolAddress((void**)&aw1, g_aw1);
    cudaGetSymbolAddress((void**)&dd0, g_d0);
    cudaGetSymbolAddress((void**)&dd1, g_d1);
    cudaGetSymbolAddress((void**)&Whv, g_Whv);
    cudaGetSymbolAddress((void**)&Whso, g_Whso);
    cudaGetSymbolAddress((void**)&Whaw, g_Whaw);
    cudaGetSymbolAddress((void**)&Whf0, g_Whf0);
    cudaGetSymbolAddress((void**)&Whf1, g_Whf1);
    cudaGetSymbolAddress((void**)&bf, g_bf);

    dim3 blk(256);
    const int MT = (NROWS + 127) / 128;   // 306

    // --- fused weight prep: 3 launches ---
    transpose_batch_kernel<<<dim3(8, 8, 3), dim3(32, 8)>>>(W_v, W_so, W_aw,
                                                           Whv, Whso, Whaw);
    wfprep_kernel<<<dim3(16, 2), blk>>>(W_o, W_agg, Whf0, Whf1);
    fuse_bias_kernel<<<1, DMODEL>>>(b_o, b_agg, W_agg, bf);

    // --- big projections ---
    gemm_hmma<256, 1><<<dim3(4, MT), blk>>>(flat0, flat0, 4, Whv, Whv, 4, b_v, value0, NROWS);
    gemm_hmma<256, 1><<<dim3(4, MT), blk>>>(flat1, flat1, 4, Whv, Whv, 4, b_v, value1, NROWS);
    gemm_hmma<256, 0><<<dim3(4, MT), blk>>>(q0, q0, 4, Whso, Whso, 4, b_so, off0, NROWS);
    gemm_hmma<256, 0><<<dim3(4, MT), blk>>>(q1, q1, 4, Whso, Whso, 4, b_so, off1, NROWS);
    gemm_hmma<128, 0><<<dim3(2, MT), blk>>>(q0, q0, 4, Whaw, Whaw, 4, b_aw, aw0, NROWS);
    gemm_hmma<128, 0><<<dim3(2, MT), blk>>>(q1, q1, 4, Whaw, Whaw, 4, b_aw, aw1, NROWS);

    // --- joint softmax over 32 ---
    {
        int total = NROWS * NHEADS;
        softmax_kernel<<<(total + 255) / 256, 256>>>(aw0, aw1, total);
    }

    // --- deformable sampling: head-quad warps, both iters in one launch ---
    {
        int blocks = (NROWS * 2 + 7) / 8;   // 9780
        sample4_kernel<<<dim3(blocks, 2), blk>>>(value0, value1, ref,
                                                 off0, off1, aw0, aw1, dd0, dd1);
    }

    // --- fused output projection: out = d0@Whf0^T + d1@Whf1^T + bf (K=512) ---
    gemm_hmma<256, 0><<<dim3(4, MT), blk>>>(dd0, dd1, 4, Whf0, Whf1, 8, bf, out, NROWS);

    (void)in_sizes; (void)n_in; (void)out_size;
}